// round 12
// baseline (speedup 1.0000x reference)
#include <cuda_runtime.h>

#define Bv 32
#define Tv 1000
#define DINv 64
#define Hv 1024

#define NBG 4
#define NJG 64               // j-CTAs per batch group (16 j each)
#define BTILE 8
#define JTILE 16
#define NTHREADS 256
#define GRID (NBG * NJG)     // 256 CTAs, 2/SM

#define WS 16                // W row stride (floats): dense 64B rows
#define HS 10                // h row stride (floats)
#define RS 168               // red k-slice stride (floats): 672B = 21*32B
#define NKS 64               // k-slices
#define KPT 16               // k per thread (strided by 64)

__device__ unsigned int g_bar[4 * 64];          // per-group counters, 256B apart
__device__ float h_bufT[2][NBG][Hv * HS];       // h state, pre-laid-out [k*10+b]

struct Smem {
    float Ws[Hv * WS];                  // 65536 B : W slice [k][jl], jl<16
    union {
        float h_s[Hv * HS];             // 40960 B (live: gather -> end of GEMM)
        float red[NKS * RS];            // 43008 B (live: after GEMM -> reduce)
    } u;
};
// total = 108544 B/CTA, x2 CTAs = 217088 B/SM

struct UinSmem {
    float2 xs2[DINv * 65];
    float  wis[DINv * 130];
};

// ---------------------------------------------------------------------------
// Phase 1: u_in = x @ W_in^T + b -> out ; resets step counters.
// ---------------------------------------------------------------------------
__global__ void __launch_bounds__(256)
esn_uin_kernel(const float* __restrict__ x, const float* __restrict__ Wiw,
               const float* __restrict__ Wib, float* __restrict__ out)
{
    extern __shared__ unsigned char usmem_raw[];
    UinSmem& us = *reinterpret_cast<UinSmem*>(usmem_raw);

    if (blockIdx.x == 0 && threadIdx.x < 4) g_bar[threadIdx.x * 64] = 0u;

    const int tid = threadIdx.x;
    const int R0  = blockIdx.x * 64;

    {
        const int kk = tid & 63;
        for (int r = tid >> 6; r < 64; r += 4) {
            float v = x[(size_t)(R0 + r) * DINv + kk];
            us.xs2[kk * 65 + r] = make_float2(v, v);
        }
    }

    const int jp = tid & 63;
    const int rq = tid >> 6;
    const unsigned wis_s = (unsigned)__cvta_generic_to_shared(us.wis);
    const unsigned xs_s  = (unsigned)__cvta_generic_to_shared(us.xs2);

    for (int jc = 0; jc < 8; ++jc) {
        __syncthreads();
        for (int idx = tid; idx < 128 * DINv; idx += 256) {
            int jj = idx >> 6, kk = idx & 63;
            us.wis[kk * 130 + jj] = Wiw[(jc * 128 + jj) * DINv + kk];
        }
        __syncthreads();

        float2 bias2 = *(const float2*)&Wib[jc * 128 + 2 * jp];
        unsigned long long b2;
        asm("mov.b64 %0,{%1,%2};" : "=l"(b2) : "f"(bias2.x), "f"(bias2.y));

        #pragma unroll
        for (int rg = 0; rg < 4; ++rg) {
            unsigned long long acc[4];
            #pragma unroll
            for (int r = 0; r < 4; ++r) acc[r] = b2;

            unsigned wa = wis_s + (2 * jp) * 4;
            unsigned xa = xs_s + (rg * 16 + rq * 4) * 8;
            #pragma unroll 8
            for (int k = 0; k < DINv; ++k) {
                unsigned long long w01, x0, x1, x2, x3;
                asm("ld.shared.u64 %0,[%1];" : "=l"(w01) : "r"(wa));
                asm("ld.shared.u64 %0,[%1];" : "=l"(x0) : "r"(xa));
                asm("ld.shared.u64 %0,[%1+8];" : "=l"(x1) : "r"(xa));
                asm("ld.shared.u64 %0,[%1+16];" : "=l"(x2) : "r"(xa));
                asm("ld.shared.u64 %0,[%1+24];" : "=l"(x3) : "r"(xa));
                asm("fma.rn.f32x2 %0,%1,%2,%0;" : "+l"(acc[0]) : "l"(w01), "l"(x0));
                asm("fma.rn.f32x2 %0,%1,%2,%0;" : "+l"(acc[1]) : "l"(w01), "l"(x1));
                asm("fma.rn.f32x2 %0,%1,%2,%0;" : "+l"(acc[2]) : "l"(w01), "l"(x2));
                asm("fma.rn.f32x2 %0,%1,%2,%0;" : "+l"(acc[3]) : "l"(w01), "l"(x3));
                wa += 130 * 4;
                xa += 65 * 8;
            }

            #pragma unroll
            for (int r = 0; r < 4; ++r) {
                float fx, fy;
                asm("mov.b64 {%0,%1},%2;" : "=f"(fx), "=f"(fy) : "l"(acc[r]));
                float2* op = (float2*)&out[(size_t)(R0 + rg * 16 + rq * 4 + r) * Hv
                                           + jc * 128 + 2 * jp];
                *op = make_float2(fx, fy);
            }
        }
    }
}

// ---------------------------------------------------------------------------
// Phase 2: persistent scan, 2 CTAs/SM (16 warps). CTA = 8b x 16j tile.
// thread = 4j x 8b block over 16 strided k. shfl-merged half reduce.
// ---------------------------------------------------------------------------
__global__ void __launch_bounds__(NTHREADS, 2)
esn_scan_kernel(const float* __restrict__ W, float* __restrict__ out)
{
    extern __shared__ unsigned char smem_raw[];
    Smem& sm = *reinterpret_cast<Smem*>(smem_raw);

    const int tid  = threadIdx.x;
    const int lane = tid & 31;
    const int jt   = tid & 3;           // j-quad: j = jt*4 .. jt*4+3
    const int ks   = tid >> 2;          // k-slice 0..63 (k = ks + 64*i)
    const int grp  = blockIdx.x & (NBG - 1);
    const int jg   = blockIdx.x >> 2;   // 0..63
    const int b0   = grp * BTILE;
    const int j0   = jg * JTILE;
    unsigned* bar  = &g_bar[grp * 64];

    // epilogue mapping: b = eb, j = j0 + ej (lane<16 threads own outputs)
    const int eb   = tid >> 5;          // 0..7
    const int ej   = lane & 15;         // 0..15
    const int half = lane >> 4;         // 0..1 : ks half for reduce

    // one-time W slice: Ws[k*16 + jl] = W[j0+jl][k]  (dense 64B rows)
    {
        const int jl = tid & 15;
        for (int k = tid >> 4; k < Hv; k += 16)
            sm.Ws[k * WS + jl] = W[(size_t)(j0 + jl) * Hv + k];
    }

    const unsigned ws_s = (unsigned)__cvta_generic_to_shared(sm.Ws)
                          + (ks * WS + jt * 4) * 4;
    const unsigned hs_s = (unsigned)__cvta_generic_to_shared(sm.u.h_s)
                          + (ks * HS) * 4;
    const unsigned hs_base = (unsigned)__cvta_generic_to_shared(sm.u.h_s);

    __syncthreads();

    const float lr  = 0.9f;
    const float olr = 1.0f - lr;
    float hprev = 0.0f;

    // ---- peeled t = 0: no GEMM ----
    {
        if (lane < 16) {
            const float u0 = out[((size_t)(b0 + eb) * Tv + 0) * Hv + j0 + ej];
            float th;
            asm("tanh.approx.f32 %0, %1;" : "=f"(th) : "f"(u0));
            const float hnew = lr * th;
            hprev = hnew;
            out[((size_t)(b0 + eb) * Tv + 0) * Hv + j0 + ej] = hnew;
            h_bufT[0][grp][(j0 + ej) * HS + eb] = hnew;
        }
        __syncthreads();
        if (tid == 0)
            asm volatile("red.release.gpu.global.add.u32 [%0], 1;" :: "l"(bar));
    }

    for (int t = 1; t < Tv; ++t) {
        // prefetch u_in (read-once stream)
        float u0 = 0.0f;
        if (lane < 16) {
            const float* up = &out[((size_t)(b0 + eb) * Tv + t) * Hv + j0 + ej];
            asm("ld.global.cs.f32 %0,[%1];" : "=f"(u0) : "l"(up));
        }

        // group barrier: all 64 CTAs of this batch group finished t-1
        if (tid == 0) {
            const unsigned tgt = (unsigned)t * NJG;
            unsigned v;
            do {
                asm volatile("ld.acquire.gpu.global.u32 %0, [%1];"
                             : "=r"(v) : "l"(bar));
            } while (v < tgt);
        }
        __syncthreads();   // (A)

        // gather: 40KB linear copy via cp.async
        {
            const char* src = (const char*)&h_bufT[(t - 1) & 1][grp][0];
            #pragma unroll
            for (int i = 0; i < 10; ++i) {
                int off = (tid + i * NTHREADS) * 16;
                asm volatile("cp.async.cg.shared.global [%0], [%1], 16;"
                             :: "r"(hs_base + off), "l"(src + off));
            }
            asm volatile("cp.async.commit_group;");
            asm volatile("cp.async.wait_group 0;" ::: "memory");
        }
        __syncthreads();   // (B) h_s ready

        // GEMM: per k = 1 LDS.128 (4 W) + 4 LDS.64 (8 h) + 8 dup + 16 FFMA2
        unsigned long long a[2][8];
        #pragma unroll
        for (int q = 0; q < 2; ++q)
            #pragma unroll
            for (int b = 0; b < 8; ++b) a[q][b] = 0ull;

        {
            unsigned wa = ws_s, ha = hs_s;
            #pragma unroll
            for (int i = 0; i < KPT; ++i) {
                unsigned long long w01, w23;
                float h0, h1, h2, h3, h4, h5, h6, h7;
                asm("ld.shared.v2.u64 {%0,%1},[%2];"
                    : "=l"(w01), "=l"(w23) : "r"(wa));
                asm("ld.shared.v2.f32 {%0,%1},[%2];"    : "=f"(h0), "=f"(h1) : "r"(ha));
                asm("ld.shared.v2.f32 {%0,%1},[%2+8];"  : "=f"(h2), "=f"(h3) : "r"(ha));
                asm("ld.shared.v2.f32 {%0,%1},[%2+16];" : "=f"(h4), "=f"(h5) : "r"(ha));
                asm("ld.shared.v2.f32 {%0,%1},[%2+24];" : "=f"(h6), "=f"(h7) : "r"(ha));
                float hv[8] = {h0, h1, h2, h3, h4, h5, h6, h7};
                #pragma unroll
                for (int b = 0; b < 8; ++b) {
                    unsigned long long hd;
                    asm("mov.b64 %0,{%1,%1};" : "=l"(hd) : "f"(hv[b]));
                    asm("fma.rn.f32x2 %0,%1,%2,%0;" : "+l"(a[0][b]) : "l"(w01), "l"(hd));
                    asm("fma.rn.f32x2 %0,%1,%2,%0;" : "+l"(a[1][b]) : "l"(w23), "l"(hd));
                }
                wa += 64 * WS * 4;
                ha += 64 * HS * 4;
            }
        }

        __syncthreads();   // (C) h_s reads done before red overwrite (union)

        // k-slice partials: 1 STS.128 per b  (4 j's contiguous)
        #pragma unroll
        for (int b = 0; b < 8; ++b) {
            float x0, y0, x1, y1;
            asm("mov.b64 {%0,%1},%2;" : "=f"(x0), "=f"(y0) : "l"(a[0][b]));
            asm("mov.b64 {%0,%1},%2;" : "=f"(x1), "=f"(y1) : "l"(a[1][b]));
            *(float4*)&sm.u.red[ks * RS + b * 20 + jt * 4] =
                make_float4(x0, y0, x1, y1);
        }
        __syncthreads();   // (D) red ready

        // reduce: each thread sums its 32-slice half, then shfl-merge halves
        float ssum;
        {
            const float* rp = &sm.u.red[half * 32 * RS + eb * 20 + ej];
            float s0 = 0.f, s1 = 0.f, s2 = 0.f, s3 = 0.f;
            #pragma unroll
            for (int s = 0; s < 32; s += 4) {
                s0 += rp[(s + 0) * RS];
                s1 += rp[(s + 1) * RS];
                s2 += rp[(s + 2) * RS];
                s3 += rp[(s + 3) * RS];
            }
            float sh = (s0 + s1) + (s2 + s3);
            ssum = sh + __shfl_down_sync(0xffffffffu, sh, 16);
        }

        // epilogue (lane<16 threads own (eb, j0+ej))
        if (lane < 16) {
            const float u = u0 + ssum;
            float th;
            asm("tanh.approx.f32 %0, %1;" : "=f"(th) : "f"(u));
            const float hnew = olr * hprev + lr * th;
            hprev = hnew;

            {
                float* op = &out[((size_t)(b0 + eb) * Tv + t) * Hv + j0 + ej];
                asm volatile("st.global.cs.f32 [%0], %1;" :: "l"(op), "f"(hnew));
            }
            h_bufT[t & 1][grp][(j0 + ej) * HS + eb] = hnew;
        }

        __syncthreads();   // (E) publish + red reads done
        if (tid == 0)
            asm volatile("red.release.gpu.global.add.u32 [%0], 1;" :: "l"(bar));
    }
}

extern "C" void kernel_launch(void* const* d_in, const int* in_sizes, int n_in,
                              void* d_out, int out_size)
{
    const float* x   = (const float*)d_in[0];  // [32,1000,64]
    const float* Wiw = (const float*)d_in[1];  // [1024,64]
    const float* Wib = (const float*)d_in[2];  // [1024]
    const float* W   = (const float*)d_in[3];  // [1024,1024]
    float* out = (float*)d_out;                // [32,1000,1024]

    cudaFuncSetAttribute(esn_uin_kernel,
                         cudaFuncAttributeMaxDynamicSharedMemorySize,
                         (int)sizeof(UinSmem));
    cudaFuncSetAttribute(esn_scan_kernel,
                         cudaFuncAttributeMaxDynamicSharedMemorySize,
                         (int)sizeof(Smem));

    esn_uin_kernel<<<(Bv * Tv) / 64, 256, sizeof(UinSmem)>>>(x, Wiw, Wib, out);
    esn_scan_kernel<<<GRID, NTHREADS, sizeof(Smem)>>>(W, out);
}